// round 9
// baseline (speedup 1.0000x reference)
#include <cuda_runtime.h>
#include <cuda_bf16.h>
#include <cstdint>

// Problem constants
#define BB   256
#define TT   2048
#define IND  6
#define HID  64
#define GG   192          // 3*HID
#define DPK  64
#define NROWS (BB*TT)     // 524288
#define EPS  1e-5f
#define CH   2            // chains per GRU CTA

typedef unsigned long long u64;

// ---------------- scratch (allocation-free: __device__ globals) -------------
__device__ float g_x[(size_t)NROWS * HID];       // 128 MB : post input-proj activations
// gi J-MAJOR: index = row*GG + gate*64 + j  (warp-coalesced loads in k_gru)
// biases pre-folded: r,z gates carry b_ih+b_hh; n gate carries b_ih only.
__device__ float g_gi[(size_t)NROWS * GG];       // 402 MB
__device__ float g_hseq[(size_t)NROWS * HID];    // 128 MB : GRU hidden states [b][t][j]

// ---------------- packed f32x2 helpers --------------------------------------
__device__ __forceinline__ u64 fma2(u64 a, u64 b, u64 c) {
    u64 d;
    asm("fma.rn.f32x2 %0, %1, %2, %3;" : "=l"(d) : "l"(a), "l"(b), "l"(c));
    return d;
}
__device__ __forceinline__ u64 pack2(float a, float b) {
    u64 r;
    asm("mov.b64 %0, {%1,%2};" : "=l"(r) : "f"(a), "f"(b));
    return r;
}
__device__ __forceinline__ float psum(u64 a) {
    return __uint_as_float((unsigned)(a & 0xffffffffull)) +
           __uint_as_float((unsigned)(a >> 32));
}

// EXACT-path activations (validated rel_err ~2.5e-7 over the full recurrence).
// tanh.approx is banned inside the recurrence (R5: errors compound to ~0.15).
__device__ __forceinline__ float sigmoidf_(float x) {
    return __fdividef(1.f, 1.f + __expf(-x));
}
__device__ __forceinline__ float tanhf_(float x) {
    float e = __expf(2.f * x);
    return 1.f - __fdividef(2.f, e + 1.f);   // safe at e->inf (->1) and e->0 (->-1)
}

// ================== K1a: input proj + LN + exact GELU ======================
// one warp per (b,t) row; each lane owns output cols lane, lane+32
__global__ void k_inproj(const float* __restrict__ ce,
                         const float* __restrict__ w1,
                         const float* __restrict__ b1,
                         const float* __restrict__ g1,
                         const float* __restrict__ bb1)
{
    const int wid  = threadIdx.x >> 5;
    const int lane = threadIdx.x & 31;
    const size_t row = (size_t)blockIdx.x * 8 + wid;   // grid = NROWS/8

    const float* c = ce + row * IND;
    float v0 = b1[lane], v1 = b1[lane + 32];
#pragma unroll
    for (int i = 0; i < IND; ++i) {
        float ci = __ldg(c + i);
        v0 = fmaf(ci, w1[i * HID + lane],      v0);
        v1 = fmaf(ci, w1[i * HID + lane + 32], v1);
    }
    float s = v0 + v1;
#pragma unroll
    for (int o = 16; o; o >>= 1) s += __shfl_xor_sync(0xffffffffu, s, o);
    const float m = s * (1.f / 64.f);
    const float d0 = v0 - m, d1 = v1 - m;
    float q = d0 * d0 + d1 * d1;
#pragma unroll
    for (int o = 16; o; o >>= 1) q += __shfl_xor_sync(0xffffffffu, q, o);
    const float rs = rsqrtf(q * (1.f / 64.f) + EPS);
    const float y0 = d0 * rs * g1[lane]      + bb1[lane];
    const float y1 = d1 * rs * g1[lane + 32] + bb1[lane + 32];
    const float k = 0.70710678118654752f;
    g_x[row * HID + lane]      = 0.5f * y0 * (1.f + erff(y0 * k));
    g_x[row * HID + lane + 32] = 0.5f * y1 * (1.f + erff(y1 * k));
}

// ================== K1b: gi = x @ W_ih^T + bias  (j-major output) ==========
// gate-stationary: thread g keeps W_ih[g,:] in 32 packed-u64 registers,
// 8 rows of x staged in smem per iteration; direct coalesced output write.
// Bias folding: gates r,z get b_ih+b_hh; gate n gets b_ih only.
__global__ void __launch_bounds__(192) k_gi(const float* __restrict__ Wih,
                                            const float* __restrict__ bih,
                                            const float* __restrict__ bhh)
{
    const int g = threadIdx.x;
    u64 w[32];
    const u64* wrow = (const u64*)(Wih + g * HID);
#pragma unroll
    for (int k = 0; k < 32; ++k) w[k] = wrow[k];
    const int gate = g >> 6;
    const float bi = bih[g] + (gate < 2 ? bhh[g] : 0.f);

    __shared__ __align__(16) float x_sh[8 * HID];

    for (size_t r0 = (size_t)blockIdx.x * 8; r0 < (size_t)NROWS;
         r0 += (size_t)gridDim.x * 8) {
        if (g < 128)
            ((float4*)x_sh)[g] = ((const float4*)(g_x + r0 * HID))[g];
        __syncthreads();
#pragma unroll
        for (int rr = 0; rr < 8; ++rr) {
            u64 a0 = 0, a1 = 0;
            const ulonglong2* xv = (const ulonglong2*)(x_sh + rr * HID);
#pragma unroll
            for (int kk = 0; kk < 16; ++kk) {
                ulonglong2 p = xv[kk];
                a0 = fma2(w[2 * kk],     p.x, a0);
                a1 = fma2(w[2 * kk + 1], p.y, a1);
            }
            g_gi[(r0 + rr) * GG + g] = psum(a0) + psum(a1) + bi;
        }
        __syncthreads();
    }
}

// ================== K2: sequential GRU recurrence ===========================
// grid = 128 CTAs, block = 256 threads = 2 chains x 128 threads (4 warps each).
// K-SPLIT: same-warp lane pair (2j, 2j+1) splits the 64-wide dot (even lane
// k in [0,32), odd k in [32,64)); partials combined by shfl_xor(.,1).
// -> 48 u64 weight regs per thread (~150 total: provably no spills) and
//    2 warps per SMSP (warps 0-3 chain0, 4-7 chain1) to hide the serial
//    latency (LDS -> dot chain -> MUFU chain -> bar) that 1 warp/SMSP exposes.
// MUFU dedup: ONE sigmoid warp-instruction computes r on even lanes and z on
// odd lanes (lane-selected argument); tanh on all lanes; one extra shfl
// passes z back to even lanes -> 4 MUFU/warp/step instead of 6.
// h in 16-slot smem ring; coalesced float4 flush every 8 steps.
// gi j-major, in-place reload depth 4. One named barrier (128 thr) per step.
__global__ void __launch_bounds__(256, 1) k_gru(const float* __restrict__ Whh,
                                                const float* __restrict__ bhh)
{
    const int tid   = threadIdx.x;
    const int chain = tid >> 7;          // 0..1
    const int c     = tid & 127;
    const int j     = c >> 1;            // 0..63
    const int half  = c & 1;             // K-half
    const int odd   = half;
    const size_t brow = (size_t)blockIdx.x * CH + chain;
    const unsigned barid = 1 + chain;

    __shared__ __align__(16) float ring[16][CH][64];  // 8 KB h history

    // half of each gate's weight row: 48 u64 = 96 regs
    u64 wr[16], wz[16], wn[16];
    {
        const u64* rrow = (const u64*)(Whh + ((size_t)j        * HID) + half * 32);
        const u64* zrow = (const u64*)(Whh + ((size_t)(64 + j)  * HID) + half * 32);
        const u64* nrow = (const u64*)(Whh + ((size_t)(128 + j) * HID) + half * 32);
#pragma unroll
        for (int k = 0; k < 16; ++k) { wr[k] = rrow[k]; wz[k] = zrow[k]; wn[k] = nrow[k]; }
    }
    const float bhn = bhh[128 + j];   // only n-gate hidden bias kept (inside r*(..))

    ring[15][chain][j] = 0.f;         // h_{-1} = 0 (pair writes same value)
    float hprev = 0.f;

    const float* gib = g_gi + brow * (size_t)TT * GG + j;   // + t*GG + gate*64
    float* hbase = g_hseq + brow * (size_t)TT * HID;

    // gi block buffer: current 4 steps (12 scalars), each reloaded in place
    // right after consumption with the value 4 steps ahead (coalesced LDG.32;
    // lane pairs load the same address -> broadcast).
    float cr0 = __ldg(gib + 0 * GG), cz0 = __ldg(gib + 0 * GG + 64), cn0 = __ldg(gib + 0 * GG + 128);
    float cr1 = __ldg(gib + 1 * GG), cz1 = __ldg(gib + 1 * GG + 64), cn1 = __ldg(gib + 1 * GG + 128);
    float cr2 = __ldg(gib + 2 * GG), cz2 = __ldg(gib + 2 * GG + 64), cn2 = __ldg(gib + 2 * GG + 128);
    float cr3 = __ldg(gib + 3 * GG), cz3 = __ldg(gib + 3 * GG + 64), cn3 = __ldg(gib + 3 * GG + 128);

    asm volatile("bar.sync %0, 128;" :: "r"(barid) : "memory");

    auto step = [&](const int t, const float ir, const float iz, const float inn) {
        // half-dot over this lane's 32-wide K slice: 8x LDS.128 broadcast
        const ulonglong2* hv = (const ulonglong2*)(&ring[(t + 15) & 15][chain][half * 32]);
        u64 ar = 0, az = 0, an = 0;
#pragma unroll
        for (int kk = 0; kk < 8; ++kk) {
            const ulonglong2 p = hv[kk];
            ar = fma2(wr[2 * kk],     p.x, ar);
            az = fma2(wz[2 * kk],     p.x, az);
            an = fma2(wn[2 * kk],     p.x, an);
            ar = fma2(wr[2 * kk + 1], p.y, ar);
            az = fma2(wz[2 * kk + 1], p.y, az);
            an = fma2(wn[2 * kk + 1], p.y, an);
        }
        float pr = psum(ar);
        float pz = psum(az);
        float pn = psum(an);
        pr += __shfl_xor_sync(0xffffffffu, pr, 1);
        pz += __shfl_xor_sync(0xffffffffu, pz, 1);
        pn += __shfl_xor_sync(0xffffffffu, pn, 1);

        // lane-selected sigmoid: even lanes compute r, odd lanes compute z
        const float sarg = odd ? (iz + pz) : (ir + pr);
        const float s1   = sigmoidf_(sarg);            // r (even) / z (odd)
        const float n    = tanhf_(inn + s1 * (pn + bhn));  // meaningful on even
        const float zv   = __shfl_xor_sync(0xffffffffu, s1, 1); // even gets z
        const float hnew = fmaf(zv, hprev - n, n);     // (1-z)*n + z*h (even)

        if (!odd) ring[t & 15][chain][j] = hnew;
        hprev = hnew;                                  // garbage on odd, unused
        asm volatile("bar.sync %0, 128;" :: "r"(barid) : "memory");
    };

#pragma unroll 1
    for (int blk = 0; blk < TT / 4; ++blk) {
        const int t0 = blk * 4;
        const bool pf = (blk + 1 < TT / 4);
        const float* p = gib + (size_t)(t0 + 4) * GG;

        { const float ir = cr0, iz = cz0, inn = cn0;
          if (pf) { cr0 = __ldg(p + 0 * GG); cz0 = __ldg(p + 0 * GG + 64); cn0 = __ldg(p + 0 * GG + 128); }
          step(t0 + 0, ir, iz, inn); }
        { const float ir = cr1, iz = cz1, inn = cn1;
          if (pf) { cr1 = __ldg(p + 1 * GG); cz1 = __ldg(p + 1 * GG + 64); cn1 = __ldg(p + 1 * GG + 128); }
          step(t0 + 1, ir, iz, inn); }
        { const float ir = cr2, iz = cz2, inn = cn2;
          if (pf) { cr2 = __ldg(p + 2 * GG); cz2 = __ldg(p + 2 * GG + 64); cn2 = __ldg(p + 2 * GG + 128); }
          step(t0 + 2, ir, iz, inn); }
        { const float ir = cr3, iz = cz3, inn = cn3;
          if (pf) { cr3 = __ldg(p + 3 * GG); cz3 = __ldg(p + 3 * GG + 64); cn3 = __ldg(p + 3 * GG + 128); }
          step(t0 + 3, ir, iz, inn); }

        if (blk & 1) {
            // flush steps tb..tb+7 (ring slots (tb&15)..+7), coalesced.
            // 128 threads/chain x 1 float4 covers 8 rows x 16 float4.
            // Safe: these slots are next overwritten >= 9 barriers later.
            const int tb   = t0 - 4;             // multiple of 8
            const int sb   = tb & 15;            // 0 or 8
            const int toff = c >> 4;             // 0..7
            const int jq   = c & 15;             // float4 index within row
            const float4 v = ((const float4*)ring[sb + toff][chain])[jq];
            ((float4*)(hbase + (size_t)(tb + toff) * HID))[jq] = v;
        }
    }
}

// ================== K3: out proj + LN =======================================
// 256 threads / 8 warps; w2 packed in smem [k2][64] (conflict-free LDS.64);
// each warp processes 4 rows per iteration (MLP_p1=4), lane owns cols lane,lane+32.
__global__ void __launch_bounds__(256) k_outproj(const float* __restrict__ w2,
                                                 const float* __restrict__ b2,
                                                 const float* __restrict__ g2,
                                                 const float* __restrict__ bb2,
                                                 float* __restrict__ out)
{
    const int tid  = threadIdx.x;
    const int wid  = tid >> 5;
    const int lane = tid & 31;
    const int j0 = lane, j1 = lane + 32;

    __shared__ __align__(16) u64   w2p[32][64];     // 16 KB
    __shared__ __align__(16) float hst[8][4][64];   // 8 KB, per-warp staging

    for (int idx = tid; idx < 32 * 64; idx += 256) {
        const int k2 = idx >> 6, jj = idx & 63;
        w2p[k2][jj] = pack2(w2[(size_t)(2 * k2) * DPK + jj],
                            w2[(size_t)(2 * k2 + 1) * DPK + jj]);
    }
    __syncthreads();

    const float bo0 = b2[j0], bo1 = b2[j1];
    const float lg0 = g2[j0], lg1 = g2[j1];
    const float lb0 = bb2[j0], lb1 = bb2[j1];

    const size_t stride = (size_t)gridDim.x * 32;
    for (size_t base = (size_t)blockIdx.x * 32 + wid * 4; base < (size_t)NROWS;
         base += stride) {
        // 4 rows in flight (front-batched LDG.64s)
        const float2 h0 = ((const float2*)(g_hseq + (base + 0) * HID))[lane];
        const float2 h1 = ((const float2*)(g_hseq + (base + 1) * HID))[lane];
        const float2 h2 = ((const float2*)(g_hseq + (base + 2) * HID))[lane];
        const float2 h3 = ((const float2*)(g_hseq + (base + 3) * HID))[lane];
        ((float2*)hst[wid][0])[lane] = h0;
        ((float2*)hst[wid][1])[lane] = h1;
        ((float2*)hst[wid][2])[lane] = h2;
        ((float2*)hst[wid][3])[lane] = h3;
        __syncwarp();

        const u64* hA = (const u64*)hst[wid][0];
        const u64* hB = (const u64*)hst[wid][1];
        const u64* hC = (const u64*)hst[wid][2];
        const u64* hD = (const u64*)hst[wid][3];
        u64 aA0 = 0, aA1 = 0, aB0 = 0, aB1 = 0;
        u64 aC0 = 0, aC1 = 0, aD0 = 0, aD1 = 0;
#pragma unroll
        for (int k2 = 0; k2 < 32; ++k2) {
            const u64 w0 = w2p[k2][j0];
            const u64 w1 = w2p[k2][j1];
            const u64 pA = hA[k2];
            const u64 pB = hB[k2];
            const u64 pC = hC[k2];
            const u64 pD = hD[k2];
            aA0 = fma2(w0, pA, aA0);  aA1 = fma2(w1, pA, aA1);
            aB0 = fma2(w0, pB, aB0);  aB1 = fma2(w1, pB, aB1);
            aC0 = fma2(w0, pC, aC0);  aC1 = fma2(w1, pC, aC1);
            aD0 = fma2(w0, pD, aD0);  aD1 = fma2(w1, pD, aD1);
        }

        u64 acc0[4] = {aA0, aB0, aC0, aD0};
        u64 acc1[4] = {aA1, aB1, aC1, aD1};
#pragma unroll
        for (int rr = 0; rr < 4; ++rr) {
            float o0 = psum(acc0[rr]) + bo0;
            float o1 = psum(acc1[rr]) + bo1;
            float s = o0 + o1;
#pragma unroll
            for (int o = 16; o; o >>= 1) s += __shfl_xor_sync(0xffffffffu, s, o);
            const float m = s * (1.f / 64.f);
            const float d0 = o0 - m, d1 = o1 - m;
            float q = d0 * d0 + d1 * d1;
#pragma unroll
            for (int o = 16; o; o >>= 1) q += __shfl_xor_sync(0xffffffffu, q, o);
            const float rs = rsqrtf(q * (1.f / 64.f) + EPS);
            const size_t row = base + rr;
            out[row * DPK + j0] = d0 * rs * lg0 + lb0;
            out[row * DPK + j1] = d1 * rs * lg1 + lb1;
        }
        __syncwarp();   // hst slot reused next iteration
    }
}

// ================== launcher =================================================
extern "C" void kernel_launch(void* const* d_in, const int* in_sizes, int n_in,
                              void* d_out, int out_size)
{
    const float* drug = (const float*)d_in[0];
    const float* w1   = (const float*)d_in[1];
    const float* b1   = (const float*)d_in[2];
    const float* ln1g = (const float*)d_in[3];
    const float* ln1b = (const float*)d_in[4];
    const float* Wih  = (const float*)d_in[5];
    const float* bih  = (const float*)d_in[6];
    const float* Whh  = (const float*)d_in[7];
    const float* bhh  = (const float*)d_in[8];
    const float* w2   = (const float*)d_in[9];
    const float* b2   = (const float*)d_in[10];
    const float* ln2g = (const float*)d_in[11];
    const float* ln2b = (const float*)d_in[12];
    float* out = (float*)d_out;

    k_inproj<<<NROWS / 8, 256>>>(drug, w1, b1, ln1g, ln1b);
    k_gi<<<888, 192>>>(Wih, bih, bhh);
    k_gru<<<BB / CH, 256>>>(Whh, bhh);
    k_outproj<<<2048, 256>>>(w2, b2, ln2g, ln2b, out);
}